// round 5
// baseline (speedup 1.0000x reference)
#include <cuda_runtime.h>
#include <cuda_bf16.h>

// Problem constants (fixed by the reference)
#define BB      2
#define XX      200
#define YY      200
#define ZZ      16      // == HEIGHT, h = 1
#define CC      17
#define EMPTY_LABEL 16
#define CHOOSE  4000

#define TPB 256
#define COLS_PER_BLK 16                       // 16 cols x 16 z = 256 voxels/block
#define BLKS_PER_B (CHOOSE / COLS_PER_BLK)    // 250
#define GRID (BB * BLKS_PER_B)                // 500

// Persistent device scratch (allocation-free).
// g_cnt / g_loss start zero (static init) and are re-zeroed by the last block
// of every call, so each call/replay starts from zeros.
// g_bar / g_ticket are MONOTONIC epoch counters (never reset).
__device__ int                 g_cnt[BB * ZZ];
__device__ float               g_loss[BB];
__device__ unsigned long long  g_bar;
__device__ unsigned long long  g_ticket;

__device__ __forceinline__ void cp16(unsigned smem_addr, const void* gptr) {
    asm volatile("cp.async.cg.shared.global [%0], [%1], 16;"
                 :: "r"(smem_addr), "l"(gptr));
}

__global__ void __launch_bounds__(TPB, 4)
fused_loss(const float* __restrict__ preds,
           const int*   __restrict__ labels,
           const int*   __restrict__ sel,
           float*       __restrict__ out) {
    const int bid = blockIdx.x;
    const int tid = threadIdx.x;
    const int b  = bid / BLKS_PER_B;
    const int cb = bid % BLKS_PER_B;

    __shared__ float s_pred[COLS_PER_BLK * ZZ * CC];   // 16*272 floats = 17408B
    __shared__ int   s_lab [COLS_PER_BLK * ZZ];        // 1KB
    __shared__ int   s_col [COLS_PER_BLK];
    __shared__ int   s_zcnt[ZZ];
    __shared__ float s_w   [ZZ];

    // ---- 1. stage sel -> column indices ------------------------------------
    if (tid < COLS_PER_BLK) {
        int2 xy = __ldg((const int2*)sel + b * CHOOSE + cb * COLS_PER_BLK + tid);
        s_col[tid] = (b * XX + xy.x) * YY + xy.y;
    } else if (tid < 2 * COLS_PER_BLK) {
        s_zcnt[tid - COLS_PER_BLK] = 0;
    }
    __syncthreads();

    // ---- 2. FIRE pred fetch via cp.async (completion deferred past barrier)
    {
        const int w = tid >> 5, lane = tid & 31;
        #pragma unroll
        for (int cc = 0; cc < 2; cc++) {
            const int lc = w * 2 + cc;
            const float4* __restrict__ src =
                (const float4*)preds + (long long)s_col[lc] * 68;   // 272 floats
            unsigned dst = (unsigned)__cvta_generic_to_shared(
                               s_pred + lc * (ZZ * CC));
            cp16(dst + lane * 16,         src + lane);
            cp16(dst + (lane + 32) * 16,  src + lane + 32);
            if (lane < 4) cp16(dst + (lane + 64) * 16, src + lane + 64);
        }
        asm volatile("cp.async.commit_group;");
    }

    // ---- 3. labels via plain loads (needed for counts BEFORE barrier) ------
    if (tid < 64) {
        int lc = tid >> 2, i4 = tid & 3;
        ((int4*)s_lab)[lc * 4 + i4] =
            __ldg((const int4*)(labels + (long long)s_col[lc] * ZZ) + i4);
    }
    __syncthreads();   // labels visible (does NOT wait for cp.async)

    // ---- 4. per-(b,z) counts ------------------------------------------------
    const int lc = tid >> 4;          // local column 0..15
    const int z  = tid & 15;
    const int lab = s_lab[lc * ZZ + z];
    const bool valid = (lab != EMPTY_LABEL);
    if (valid) atomicAdd(&s_zcnt[z], 1);
    __syncthreads();
    if (tid < ZZ) {
        if (s_zcnt[tid]) atomicAdd(&g_cnt[b * ZZ + tid], s_zcnt[tid]);
    }
    __threadfence();

    // ---- 5. grid barrier (monotonic epoch counter); preds still in flight --
    __shared__ unsigned long long s_target;
    if (tid == 0) {
        unsigned long long old = atomicAdd(&g_bar, 1ULL);
        s_target = (old / GRID + 1ULL) * GRID;
    }
    __syncthreads();
    if (tid == 0) {
        volatile unsigned long long* vb = (volatile unsigned long long*)&g_bar;
        while (*vb < s_target) { __nanosleep(32); }
        __threadfence();   // acquire: all g_cnt updates visible
    }
    __syncthreads();

    // ---- 6. weights for this batch -----------------------------------------
    __shared__ int s_ci[ZZ];
    if (tid < ZZ) s_ci[tid] = g_cnt[b * ZZ + tid];
    __syncthreads();
    if (tid < ZZ) {
        int maxc = 0;
        #pragma unroll
        for (int z2 = 0; z2 < ZZ; z2++) maxc = max(maxc, s_ci[z2]);
        float maxcf = fmaxf((float)maxc, 1.0f);
        int c = s_ci[tid];
        const float LOG_RATIO = -1.0986122886681098f;   // ln(1/3)
        s_w[tid] = (c > 0) ? 3.0f * __expf(((float)c / maxcf) * LOG_RATIO) : 0.0f;
    }

    // ---- 7. now wait for preds; softmax + loss ------------------------------
    asm volatile("cp.async.wait_group 0;");
    __syncthreads();

    float val = 0.0f;
    if (valid) {
        const float* __restrict__ p = s_pred + lc * (ZZ * CC) + z * CC;
        float s = 0.0f;
        #pragma unroll
        for (int c = 0; c < CC; c++) s += __expf(p[c]);   // conflict-free LDS
        const float plab = __fdividef(__expf(p[lab]), s);
        const float ll = __logf(plab + 0.001f);
        const float wl = s_w[z] * ll;
        const float ax = fabsf(wl);
        val = (ax < 1.0f) ? 0.5f * wl * wl : (ax - 0.5f);
    }

    // ---- 8. block reduce -> per-batch atomic --------------------------------
    #pragma unroll
    for (int off = 16; off > 0; off >>= 1)
        val += __shfl_down_sync(0xffffffffu, val, off);
    __shared__ float s_warp[TPB / 32];
    const int wid = tid >> 5, lid = tid & 31;
    if (lid == 0) s_warp[wid] = val;
    __syncthreads();
    if (wid == 0) {
        float v = (lid < TPB / 32) ? s_warp[lid] : 0.0f;
        #pragma unroll
        for (int off = 4; off > 0; off >>= 1)
            v += __shfl_down_sync(0xffffffffu, v, off);
        if (lid == 0) {
            atomicAdd(&g_loss[b], v);
            __threadfence();
        }
    }
    __syncthreads();

    // ---- 9. last block: finalize + reset accumulators -----------------------
    __shared__ int s_last;
    if (tid == 0) {
        unsigned long long old = atomicAdd(&g_ticket, 1ULL);
        s_last = ((old % GRID) == (GRID - 1)) ? 1 : 0;
    }
    __syncthreads();
    if (!s_last) return;

    if (tid == 0) {
        __threadfence();  // acquire all g_loss / g_cnt updates
        int n0 = 0, n1 = 0;
        #pragma unroll
        for (int z2 = 0; z2 < ZZ; z2++) { n0 += g_cnt[z2]; n1 += g_cnt[ZZ + z2]; }
        float r0 = g_loss[0] / fmaxf((float)n0, 1.0f);
        float r1 = g_loss[1] / fmaxf((float)n1, 1.0f);
        out[0] = 0.5f * (r0 + r1);
        // reset for next call (graph replay / re-validation)
        #pragma unroll
        for (int z2 = 0; z2 < BB * ZZ; z2++) g_cnt[z2] = 0;
        g_loss[0] = 0.0f;
        g_loss[1] = 0.0f;
    }
}

extern "C" void kernel_launch(void* const* d_in, const int* in_sizes, int n_in,
                              void* d_out, int out_size) {
    const float* preds  = nullptr;
    const int*   labels = nullptr;
    const int*   sel    = nullptr;
    for (int i = 0; i < n_in; i++) {
        if (in_sizes[i] == BB * XX * YY * ZZ * CC)      preds  = (const float*)d_in[i];
        else if (in_sizes[i] == BB * XX * YY * ZZ)      labels = (const int*)d_in[i];
        else if (in_sizes[i] == BB * CHOOSE * 2)        sel    = (const int*)d_in[i];
    }
    fused_loss<<<GRID, TPB>>>(preds, labels, sel, (float*)d_out);
}